// round 10
// baseline (speedup 1.0000x reference)
#include <cuda_runtime.h>
#include <cuda_bf16.h>
#include <cstdint>
#include <math.h>

// ---------------------------------------------------------------------------
// HATBlock — Round 10: R9 with memset-launch removed (g_part zeroed inside
// k_winpart) so ncu -s 5 -c 1 lands on the QKV GEMM.
// B=4, C=256, H=W=192, WS=8, NH=8, HD=32
// ---------------------------------------------------------------------------

#define BATCH 4
#define DIM   256
#define HH    192
#define WW_   192
#define NWH   24
#define NWIN  (BATCH*NWH*NWH)   // 2304
#define NTOK  (NWIN*64)         // 147456
#define NH    8
#define TOK_PER_B (HH*WW_)      // 36864

typedef unsigned long long u64;
typedef unsigned int u32;

// -------------------- scratch (device globals; no runtime alloc) -----------
__device__ float g_wins[(size_t)NTOK*256];     // wins / y (fp32)
__device__ float g_h   [(size_t)NTOK*256];     // attn-out bf16 alias / final fp32
__device__ float g_big [(size_t)NTOK*512];     // qkv(768) / hidden(1024) as bf16
__device__ float g_part[1024];                 // pooled sums [B,256]
__device__ float g_gate[BATCH*256];
__device__ float g_wb  [786432/2];             // bf16 weights, transposed [N,K]

__device__ __forceinline__ float gelu_exact(float x) {
    return 0.5f * x * (1.0f + erff(x * 0.70710678118654752f));
}

__device__ __forceinline__ void cp_async16(void* smem, const void* gmem) {
    unsigned s = (unsigned)__cvta_generic_to_shared(smem);
    asm volatile("cp.async.ca.shared.global [%0], [%1], 16;" :: "r"(s), "l"(gmem));
}
__device__ __forceinline__ void cp_commit() { asm volatile("cp.async.commit_group;"); }
__device__ __forceinline__ void cp_wait2()  { asm volatile("cp.async.wait_group 2;" ::: "memory"); }

__device__ __forceinline__ void mma_bf16(float* c, const u32* a, const u32* b) {
    asm volatile(
        "mma.sync.aligned.m16n8k16.row.col.f32.bf16.bf16.f32 "
        "{%0,%1,%2,%3},{%4,%5,%6,%7},{%8,%9},{%0,%1,%2,%3};"
        : "+f"(c[0]), "+f"(c[1]), "+f"(c[2]), "+f"(c[3])
        : "r"(a[0]), "r"(a[1]), "r"(a[2]), "r"(a[3]), "r"(b[0]), "r"(b[1]));
}

__device__ __forceinline__ void ldsm4(u32& r0, u32& r1, u32& r2, u32& r3, u32 addr) {
    asm volatile("ldmatrix.sync.aligned.m8n8.x4.shared.b16 {%0,%1,%2,%3}, [%4];"
                 : "=r"(r0), "=r"(r1), "=r"(r2), "=r"(r3) : "r"(addr));
}

__device__ __forceinline__ u32 packbf(float a, float b) {
    __nv_bfloat162 t = __float22bfloat162_rn(make_float2(a, b));
    return *(u32*)&t;
}

// -------------------- weight prep: fp32 [K,N] -> bf16 [N,K] ----------------
__global__ void k_wprep(const float* __restrict__ in, __nv_bfloat16* __restrict__ out,
                        int K, int N) {
    __shared__ float tile[32][33];
    int n0 = blockIdx.x * 32, k0 = blockIdx.y * 32;
    for (int r = threadIdx.y; r < 32; r += 8)
        tile[r][threadIdx.x] = in[(size_t)(k0 + r) * N + n0 + threadIdx.x];
    __syncthreads();
    for (int r = threadIdx.y; r < 32; r += 8)
        out[(size_t)(n0 + r) * K + k0 + threadIdx.x] = __float2bfloat16_rn(tile[threadIdx.x][r]);
}

// -------------------- window partition (+ zero pooled sums) ----------------
__global__ void k_winpart(const float* __restrict__ x, float* __restrict__ wins,
                          float* __restrict__ part) {
    int w0 = blockIdx.x * 32, hh = blockIdx.y;
    int b = blockIdx.z >> 3, c0 = (blockIdx.z & 7) * 32;
    if (blockIdx.x == 0 && blockIdx.y == 0 && blockIdx.z == 0) {
        int t = threadIdx.y * 32 + threadIdx.x;
#pragma unroll
        for (int i = 0; i < 4; i++) part[t + 256*i] = 0.f;
    }
    __shared__ float tile[32][33];
    for (int cc = threadIdx.y; cc < 32; cc += 8)
        tile[cc][threadIdx.x] =
            x[(((size_t)b*256 + c0 + cc)*HH + hh)*WW_ + w0 + threadIdx.x];
    __syncthreads();
    int hw = hh >> 3, i = hh & 7;
    for (int wi = threadIdx.y; wi < 32; wi += 8) {
        int w = w0 + wi, ww = w >> 3, j = w & 7;
        size_t t = (((size_t)b*NWH + hw)*NWH + ww)*64 + i*8 + j;
        wins[t*256 + c0 + threadIdx.x] = tile[threadIdx.x][wi];
    }
}

// -------------------- window reverse: z[t,c] -> out[B,C,H,W] ---------------
__global__ void k_winrev(const float* __restrict__ z, float* __restrict__ out) {
    int w0 = blockIdx.x * 32, hh = blockIdx.y;
    int b = blockIdx.z >> 3, c0 = (blockIdx.z & 7) * 32;
    __shared__ float tile[32][33];
    int hw = hh >> 3, i = hh & 7;
    for (int wi = threadIdx.y; wi < 32; wi += 8) {
        int w = w0 + wi, ww = w >> 3, j = w & 7;
        size_t t = (((size_t)b*NWH + hw)*NWH + ww)*64 + i*8 + j;
        tile[wi][threadIdx.x] = z[t*256 + c0 + threadIdx.x];
    }
    __syncthreads();
    for (int cc = threadIdx.y; cc < 32; cc += 8)
        out[(((size_t)b*256 + c0 + cc)*HH + hh)*WW_ + w0 + threadIdx.x] =
            tile[threadIdx.x][cc];
}

// ============================================================================
// GEMM 1: A cached in smem bf16 (optionally with fused gate+LN from fp32 gmem).
// 256 threads = 8 warps (4 m x 2 n), warp tile 32x64, K chunk 32, 4-stage B.
// ============================================================================
#define AB_STR 264
#define B_STR  40
#define SMA_BR 67584
#define SMA_SCOL 108544
#define SMA_SMEM 109056

__global__ void __launch_bounds__(256, 2)
k_gemm_smA(const void* __restrict__ Ain, int a_bf16,
           const float* __restrict__ lng, const float* __restrict__ lnb,
           const float* __restrict__ gate,
           const __nv_bfloat16* __restrict__ Wt,
           const float* __restrict__ bias,
           const float* __restrict__ R,
           void* __restrict__ Cout, int c_bf16, int act,
           int Nfull, float* __restrict__ pool)
{
    extern __shared__ char smem[];
    __nv_bfloat16* Ab = (__nv_bfloat16*)smem;
    char*  Bring = smem + SMA_BR;
    float* scol = (float*)(smem + SMA_SCOL);
    const u32 sbase = (u32)__cvta_generic_to_shared(smem);

    const int tid = threadIdx.x, lane = tid & 31, wid = tid >> 5;
    const int g = lane >> 2, tig = lane & 3;
    const int arow = (wid & 3) * 32;
    const int bcol = (wid >> 2) * 64;
    const int m0 = blockIdx.x * 128;
    const int b  = m0 / TOK_PER_B;

    const int a_dr = (lane & 7) | (((lane >> 3) & 1) << 3);
    const int a_dk = (lane >> 4) << 3;
    const int quad = lane >> 3;
    const int b_dc = (lane & 7) + ((quad & 2) ? 8 : 0);
    const int b_dk = (quad & 1) << 3;

    // ---- load A ----
    if (a_bf16) {
        const __nv_bfloat16* Ag = (const __nv_bfloat16*)Ain + (size_t)m0 * 256;
#pragma unroll
        for (int i = 0; i < 16; i++) {
            int idx = tid + 256*i;
            int r = idx >> 5, c8 = idx & 31;
            cp_async16(Ab + r*AB_STR + c8*8, Ag + (size_t)r*256 + c8*8);
        }
        cp_commit();
    } else {
        const float* Ag = (const float*)Ain + (size_t)m0 * 256;
        const float* gp = gate ? (gate + b*256) : nullptr;
        float gv[8], lg[8], lb[8];
#pragma unroll
        for (int j = 0; j < 8; j++) {
            int c = lane*8 + j;
            gv[j] = gp ? gp[c] : 1.f;
            lg[j] = lng[c]; lb[j] = lnb[c];
        }
#pragma unroll 1
        for (int i = 0; i < 16; i++) {
            int r = wid*16 + i;
            const float4* rp = (const float4*)(Ag + (size_t)r * 256 + lane*8);
            float4 va = rp[0], vb = rp[1];
            float v[8] = {va.x, va.y, va.z, va.w, vb.x, vb.y, vb.z, vb.w};
            float s = 0.f, s2 = 0.f;
#pragma unroll
            for (int j = 0; j < 8; j++) {
                v[j] *= gv[j]; s += v[j]; s2 += v[j]*v[j];
            }
#pragma unroll
            for (int o = 16; o; o >>= 1) {
                s  += __shfl_xor_sync(0xffffffffu, s,  o);
                s2 += __shfl_xor_sync(0xffffffffu, s2, o);
            }
            float mean = s * (1.f/256.f);
            float var  = s2 * (1.f/256.f) - mean*mean;
            float inv  = rsqrtf(var + 1e-5f);
#pragma unroll
            for (int k = 0; k < 4; k++) {
                float n0 = (v[2*k  ]-mean)*inv*lg[2*k  ] + lb[2*k  ];
                float n1 = (v[2*k+1]-mean)*inv*lg[2*k+1] + lb[2*k+1];
                *(u32*)&Ab[r*AB_STR + lane*8 + 2*k] = packbf(n0, n1);
            }
        }
        __syncthreads();
    }

    const int NY = Nfull >> 7;
    const int KT = 8;
    const int TOT = NY * KT;

    auto fillB = [&](int c) {
        int ny2 = c >> 3, kt2 = c & 7, st = c & 3;
        __nv_bfloat16* Bs = (__nv_bfloat16*)(Bring + st*10240);
        const __nv_bfloat16* Wg = Wt + (size_t)(ny2*128) * 256 + kt2*32;
#pragma unroll
        for (int i = 0; i < 2; i++) {
            int idx = tid + 256*i;
            int row = idx >> 2, seg = idx & 3;
            cp_async16(Bs + row*B_STR + seg*8, Wg + (size_t)row*256 + seg*8);
        }
        cp_commit();
    };
    fillB(0); fillB(1); fillB(2);

    int ci = 0;
    for (int ny = 0; ny < NY; ny++) {
        float acc[2][8][4];
#pragma unroll
        for (int i = 0; i < 2; i++)
#pragma unroll
            for (int j = 0; j < 8; j++)
#pragma unroll
                for (int q = 0; q < 4; q++) acc[i][j][q] = 0.f;

        for (int kt = 0; kt < KT; kt++, ci++) {
            cp_wait2();
            __syncthreads();
            const u32 bsb = sbase + SMA_BR + (u32)(ci & 3)*10240;
#pragma unroll
            for (int ks = 0; ks < 2; ks++) {
                const int kb = kt*32 + ks*16;
                u32 af[2][4], bf[8][2];
#pragma unroll
                for (int mt = 0; mt < 2; mt++) {
                    u32 aaddr = sbase + (u32)(((arow + mt*16 + a_dr)*AB_STR + kb + a_dk) * 2);
                    ldsm4(af[mt][0], af[mt][1], af[mt][2], af[mt][3], aaddr);
                }
#pragma unroll
                for (int p = 0; p < 4; p++) {
                    u32 baddr = bsb + (u32)(((bcol + p*16 + b_dc)*B_STR + ks*16 + b_dk) * 2);
                    ldsm4(bf[2*p][0], bf[2*p][1], bf[2*p+1][0], bf[2*p+1][1], baddr);
                }
#pragma unroll
                for (int mt = 0; mt < 2; mt++)
#pragma unroll
                    for (int nt = 0; nt < 8; nt++)
                        mma_bf16(acc[mt][nt], af[mt], bf[nt]);
            }
            if (ci + 3 < TOT) fillB(ci + 3);
            else cp_commit();
        }

        const int ncol0 = ny * 128;
        if (c_bf16) {
            __nv_bfloat16* Cb = (__nv_bfloat16*)Cout;
#pragma unroll
            for (int nt = 0; nt < 8; nt++) {
                int colG = ncol0 + bcol + nt*8 + 2*tig;
                float b0 = bias[colG], b1 = bias[colG + 1];
#pragma unroll
                for (int mt = 0; mt < 2; mt++) {
                    size_t r0 = (size_t)m0 + arow + mt*16 + g;
                    size_t r1 = r0 + 8;
                    float v00 = acc[mt][nt][0] + b0, v01 = acc[mt][nt][1] + b1;
                    float v10 = acc[mt][nt][2] + b0, v11 = acc[mt][nt][3] + b1;
                    if (act) {
                        v00 = gelu_exact(v00); v01 = gelu_exact(v01);
                        v10 = gelu_exact(v10); v11 = gelu_exact(v11);
                    }
                    *(u32*)((__nv_bfloat16*)Cb + r0*Nfull + colG) = packbf(v00, v01);
                    *(u32*)((__nv_bfloat16*)Cb + r1*Nfull + colG) = packbf(v10, v11);
                }
            }
        } else {
            float* Cf = (float*)Cout;
            float psum[8][2];
#pragma unroll
            for (int nt = 0; nt < 8; nt++) { psum[nt][0] = 0.f; psum[nt][1] = 0.f; }
#pragma unroll
            for (int nt = 0; nt < 8; nt++) {
                int colG = ncol0 + bcol + nt*8 + 2*tig;
                float b0 = bias[colG], b1 = bias[colG + 1];
#pragma unroll
                for (int mt = 0; mt < 2; mt++) {
                    size_t r0 = (size_t)m0 + arow + mt*16 + g;
                    size_t r1 = r0 + 8;
                    float2 q0 = *(const float2*)(R + r0*Nfull + colG);
                    float2 q1 = *(const float2*)(R + r1*Nfull + colG);
                    float v00 = acc[mt][nt][0] + b0 + q0.x, v01 = acc[mt][nt][1] + b1 + q0.y;
                    float v10 = acc[mt][nt][2] + b0 + q1.x, v11 = acc[mt][nt][3] + b1 + q1.y;
                    *(float2*)(Cf + r0*Nfull + colG) = make_float2(v00, v01);
                    *(float2*)(Cf + r1*Nfull + colG) = make_float2(v10, v11);
                    psum[nt][0] += v00 + v10; psum[nt][1] += v01 + v11;
                }
            }
            if (pool) {
                __syncthreads();
                if (tid < 128) scol[tid] = 0.f;
                __syncthreads();
#pragma unroll
                for (int nt = 0; nt < 8; nt++) {
                    int colL = bcol + nt*8 + 2*tig;
                    atomicAdd(&scol[colL],     psum[nt][0]);
                    atomicAdd(&scol[colL + 1], psum[nt][1]);
                }
                __syncthreads();
                if (tid < 128) atomicAdd(pool + b*256 + ncol0 + tid, scol[tid]);
                __syncthreads();
            }
        }
    }
}

// ============================================================================
// GEMM 2 (MLP2): A bf16 streamed [M,1024], Wt bf16 [256,1024], N-loop (2).
// ============================================================================
#define SA_SMEM 81920
__global__ void __launch_bounds__(256, 2)
k_gemm_sA(const __nv_bfloat16* __restrict__ Ain,
          const __nv_bfloat16* __restrict__ Wt,
          const float* __restrict__ bias,
          const float* __restrict__ R,
          const float* __restrict__ gate,
          float* __restrict__ Cout)
{
    extern __shared__ char smem[];
    const u32 sbase = (u32)__cvta_generic_to_shared(smem);
    const int tid = threadIdx.x, lane = tid & 31, wid = tid >> 5;
    const int g = lane >> 2, tig = lane & 3;
    const int arow = (wid & 3) * 32;
    const int bcol = (wid >> 2) * 64;
    const int m0 = blockIdx.x * 128;
    const int b  = m0 / TOK_PER_B;
    const int KT = 32, NY = 2, TOT = 64;

    const int a_dr = (lane & 7) | (((lane >> 3) & 1) << 3);
    const int a_dk = (lane >> 4) << 3;
    const int quad = lane >> 3;
    const int b_dc = (lane & 7) + ((quad & 2) ? 8 : 0);
    const int b_dk = (quad & 1) << 3;

    const __nv_bfloat16* Ag = Ain + (size_t)m0 * 1024;

    auto fillC = [&](int c) {
        int ny2 = c >> 5, kt2 = c & 31, st = c & 3;
        __nv_bfloat16* As = (__nv_bfloat16*)(smem + st*10240);
        __nv_bfloat16* Bs = (__nv_bfloat16*)(smem + 40960 + st*10240);
        const __nv_bfloat16* Wg = Wt + (size_t)(ny2*128) * 1024 + kt2*32;
        const __nv_bfloat16* Ac = Ag + kt2*32;
#pragma unroll
        for (int i = 0; i < 2; i++) {
            int idx = tid + 256*i;
            int row = idx >> 2, seg = idx & 3;
            cp_async16(As + row*B_STR + seg*8, Ac + (size_t)row*1024 + seg*8);
            cp_async16(Bs + row*B_STR + seg*8, Wg + (size_t)row*1024 + seg*8);
        }
        cp_commit();
    };
    fillC(0); fillC(1); fillC(2);

    int ci = 0;
    for (int ny = 0; ny < NY; ny++) {
        float acc[2][8][4];
#pragma unroll
        for (int i = 0; i < 2; i++)
#pragma unroll
            for (int j = 0; j < 8; j++)
#pragma unroll
                for (int q = 0; q < 4; q++) acc[i][j][q] = 0.f;

        for (int kt = 0; kt < KT; kt++, ci++) {
            cp_wait2();
            __syncthreads();
            int st = ci & 3;
            const u32 asb = sbase + (u32)st*10240;
            const u32 bsb = sbase + 40960u + (u32)st*10240;
#pragma unroll
            for (int ks = 0; ks < 2; ks++) {
                u32 af[2][4], bf[8][2];
#pragma unroll
                for (int mt = 0; mt < 2; mt++) {
                    u32 aaddr = asb + (u32)(((arow + mt*16 + a_dr)*B_STR + ks*16 + a_dk) * 2);
                    ldsm4(af[mt][0], af[mt][1], af[mt][2], af[mt][3], aaddr);
                }
#pragma unroll
                for (int p = 0; p < 4; p++) {
                    u32 baddr = bsb + (u32)(((bcol + p*16 + b_dc)*B_STR + ks*16 + b_dk) * 2);
                    ldsm4(bf[2*p][0], bf[2*p][1], bf[2*p+1][0], bf[2*p+1][1], baddr);
                }
#pragma unroll
                for (int mt = 0; mt < 2; mt++)
#pragma unroll
                    for (int nt = 0; nt < 8; nt++)
                        mma_bf16(acc[mt][nt], af[mt], bf[nt]);
            }
            if (ci + 3 < TOT) fillC(ci + 3);
            else cp_commit();
        }

        const int ncol0 = ny * 128;
#pragma unroll
        for (int nt = 0; nt < 8; nt++) {
            int colG = ncol0 + bcol + nt*8 + 2*tig;
            float b0 = bias[colG], b1 = bias[colG + 1];
            float g0 = gate[b*256 + colG], g1 = gate[b*256 + colG + 1];
#pragma unroll
            for (int mt = 0; mt < 2; mt++) {
                size_t r0 = (size_t)m0 + arow + mt*16 + g;
                size_t r1 = r0 + 8;
                float2 q0 = *(const float2*)(R + r0*256 + colG);
                float2 q1 = *(const float2*)(R + r1*256 + colG);
                float v00 = acc[mt][nt][0] + b0 + q0.x*g0, v01 = acc[mt][nt][1] + b1 + q0.y*g1;
                float v10 = acc[mt][nt][2] + b0 + q1.x*g0, v11 = acc[mt][nt][3] + b1 + q1.y*g1;
                *(float2*)(Cout + r0*256 + colG) = make_float2(v00, v01);
                *(float2*)(Cout + r1*256 + colG) = make_float2(v10, v11);
            }
        }
    }
}

// ============================================================================
// Tensor-core window attention: one warp per (window, head).
// ============================================================================
__global__ void __launch_bounds__(128) k_attn_tc(const __nv_bfloat16* __restrict__ qkv,
                                                 const float* __restrict__ rel_bias,
                                                 __nv_bfloat16* __restrict__ o) {
    __shared__ __align__(16) __nv_bfloat16 VtAll[4][32][72];
    __shared__ float sbAll[4][226];

    const int lane = threadIdx.x & 31;
    const int wid  = threadIdx.x >> 5;
    const int g = lane >> 2, tig = lane & 3;
    const int win = blockIdx.x;
    const int h = blockIdx.y * 4 + wid;

    __nv_bfloat16 (*Vt)[72] = VtAll[wid];
    float* sb = sbAll[wid];
    const u32 vtb = (u32)__cvta_generic_to_shared(&VtAll[wid][0][0]);

    const int quad = lane >> 3;
    const int v_dc = (lane & 7) + ((quad & 2) ? 8 : 0);
    const int v_dk = (quad & 1) << 3;

    const __nv_bfloat16* qw = qkv + (size_t)win * 64 * 768 + h * 32;
    const __nv_bfloat16* kw = qw + 256;
    const __nv_bfloat16* vw = qw + 512;

    for (int r = lane; r < 225; r += 32) sb[r] = rel_bias[r*NH + h];

#pragma unroll
    for (int i = 0; i < 32; i++) {
        int idx = lane + 32*i;
        int n = idx >> 4, dp = idx & 15;
        u32 u = *(const u32*)(vw + (size_t)n*768 + 2*dp);
        __nv_bfloat162 v2 = *(__nv_bfloat162*)&u;
        Vt[2*dp  ][n] = v2.x;
        Vt[2*dp+1][n] = v2.y;
    }
    __syncwarp();

    u32 aQ[2][4][4];
#pragma unroll
    for (int ks = 0; ks < 2; ks++) {
        const int kc = 16*ks + 2*tig;
#pragma unroll
        for (int mt = 0; mt < 4; mt++) {
            const __nv_bfloat16* q0 = qw + (size_t)(mt*16 + g)*768 + kc;
            aQ[ks][mt][0] = *(const u32*)(q0);
            aQ[ks][mt][1] = *(const u32*)(q0 + 8*768);
            aQ[ks][mt][2] = *(const u32*)(q0 + 8);
            aQ[ks][mt][3] = *(const u32*)(q0 + 8*768 + 8);
        }
    }

    float O[4][4][4];
#pragma unroll
    for (int a = 0; a < 4; a++)
#pragma unroll
        for (int bq = 0; bq < 4; bq++)
#pragma unroll
            for (int c = 0; c < 4; c++) O[a][bq][c] = 0.f;
    float mrow[8], lrow[8];
#pragma unroll
    for (int r = 0; r < 8; r++) { mrow[r] = -1e30f; lrow[r] = 0.f; }

#pragma unroll 1
    for (int ck = 0; ck < 2; ck++) {
        float S[4][4][4];
#pragma unroll
        for (int a = 0; a < 4; a++)
#pragma unroll
            for (int bq = 0; bq < 4; bq++)
#pragma unroll
                for (int c = 0; c < 4; c++) S[a][bq][c] = 0.f;

#pragma unroll
        for (int ks = 0; ks < 2; ks++) {
            const int kc = 16*ks + 2*tig;
            u32 bK[4][2];
#pragma unroll
            for (int nt = 0; nt < 4; nt++) {
                const __nv_bfloat16* k0 = kw + (size_t)(ck*32 + nt*8 + g)*768 + kc;
                bK[nt][0] = *(const u32*)(k0);
                bK[nt][1] = *(const u32*)(k0 + 8);
            }
#pragma unroll
            for (int mt = 0; mt < 4; mt++)
#pragma unroll
                for (int nt = 0; nt < 4; nt++)
                    mma_bf16(S[mt][nt], aQ[ks][mt], bK[nt]);
        }

#pragma unroll
        for (int mt = 0; mt < 4; mt++)
#pragma unroll
            for (int nt = 0; nt < 4; nt++)
#pragma unroll
                for (int rr = 0; rr < 2; rr++)
#pragma unroll
                    for (int e = 0; e < 2; e++) {
                        int di = 2*mt + rr - (4*ck + nt) + 7;
                        int dj = g - (2*tig + e) + 7;
                        S[mt][nt][rr*2+e] = S[mt][nt][rr*2+e] * 0.17677669529663687f
                                          + sb[di*15 + dj];
                    }

#pragma unroll
        for (int mt = 0; mt < 4; mt++)
#pragma unroll
            for (int rr = 0; rr < 2; rr++) {
                const int r8 = mt*2 + rr;
                float mloc = -1e30f;
#pragma unroll
                for (int nt = 0; nt < 4; nt++) {
                    mloc = fmaxf(mloc, S[mt][nt][rr*2]);
                    mloc = fmaxf(mloc, S[mt][nt][rr*2+1]);
                }
                mloc = fmaxf(mloc, __shfl_xor_sync(0xffffffffu, mloc, 1));
                mloc = fmaxf(mloc, __shfl_xor_sync(0xffffffffu, mloc, 2));
                float newm = fmaxf(mrow[r8], mloc);
                float fsc = __expf(mrow[r8] - newm);
                mrow[r8] = newm;
                float rsum = 0.f;
#pragma unroll
                for (int nt = 0; nt < 4; nt++) {
                    float p0 = __expf(S[mt][nt][rr*2]   - newm);
                    float p1 = __expf(S[mt][nt][rr*2+1] - newm);
                    S[mt][nt][rr*2] = p0; S[mt][nt][rr*2+1] = p1;
                    rsum += p0 + p1;
                }
                rsum += __shfl_xor_sync(0xffffffffu, rsum, 1);
                rsum += __shfl_xor_sync(0xffffffffu, rsum, 2);
                lrow[r8] = lrow[r8]*fsc + rsum;
#pragma unroll
                for (int nt2 = 0; nt2 < 4; nt2++) {
                    O[mt][nt2][rr*2]   *= fsc;
                    O[mt][nt2][rr*2+1] *= fsc;
                }
            }

#pragma unroll
        for (int ks2 = 0; ks2 < 2; ks2++) {
            u32 bV[4][2];
#pragma unroll
            for (int p = 0; p < 2; p++) {
                u32 vaddr = vtb + (u32)(((p*16 + v_dc)*72 + ck*32 + ks2*16 + v_dk) * 2);
                ldsm4(bV[2*p][0], bV[2*p][1], bV[2*p+1][0], bV[2*p+1][1], vaddr);
            }
#pragma unroll
            for (int mt = 0; mt < 4; mt++) {
                u32 pa[4];
                pa[0] = packbf(S[mt][2*ks2  ][0], S[mt][2*ks2  ][1]);
                pa[1] = packbf(S[mt][2*ks2  ][2], S[mt][2*ks2  ][3]);
                pa[2] = packbf(S[mt][2*ks2+1][0], S[mt][2*ks2+1][1]);
                pa[3] = packbf(S[mt][2*ks2+1][2], S[mt][2*ks2+1][3]);
#pragma unroll
                for (int nt2 = 0; nt2 < 4; nt2++)
                    mma_bf16(O[mt][nt2], pa, bV[nt2]);
            }
        }
    }

    float invl[8];
#pragma unroll
    for (int r = 0; r < 8; r++) invl[r] = 1.f / lrow[r];
    __nv_bfloat16* ob = o + (size_t)win * 64 * 256 + h * 32;
#pragma unroll
    for (int mt = 0; mt < 4; mt++)
#pragma unroll
        for (int nt2 = 0; nt2 < 4; nt2++) {
            __nv_bfloat16* p0 = ob + (size_t)(mt*16 + g)*256 + nt2*8 + 2*tig;
            *(u32*)(p0)         = packbf(O[mt][nt2][0]*invl[2*mt],   O[mt][nt2][1]*invl[2*mt]);
            *(u32*)(p0 + 8*256) = packbf(O[mt][nt2][2]*invl[2*mt+1], O[mt][nt2][3]*invl[2*mt+1]);
        }
}

// -------------------- SE gate from completed pooled sums --------------------
__global__ void __launch_bounds__(256) k_pool_gate(const float* __restrict__ part,
                                                   const float* __restrict__ w1,
                                                   const float* __restrict__ b1,
                                                   const float* __restrict__ w2,
                                                   const float* __restrict__ b2,
                                                   float* __restrict__ gate) {
    int b = blockIdx.x;
    float pooled = part[b*256 + threadIdx.x] * (1.f / (float)TOK_PER_B);
    __shared__ float sp[256];
    __shared__ float hid[16];
    sp[threadIdx.x] = pooled;
    __syncthreads();
    if (threadIdx.x < 16) {
        float a = b1[threadIdx.x];
        for (int c = 0; c < 256; c++) a = fmaf(sp[c], w1[c*16 + threadIdx.x], a);
        hid[threadIdx.x] = fmaxf(a, 0.f);
    }
    __syncthreads();
    float g = b2[threadIdx.x];
#pragma unroll
    for (int j = 0; j < 16; j++) g = fmaf(hid[j], w2[j*256 + threadIdx.x], g);
    gate[b*256 + threadIdx.x] = 1.f / (1.f + __expf(-g));
}

// ---------------------------------------------------------------------------
extern "C" void kernel_launch(void* const* d_in, const int* in_sizes, int n_in,
                              void* d_out, int out_size) {
    const float* x      = (const float*)d_in[0];
    const float* n1_g   = (const float*)d_in[1];
    const float* n1_b   = (const float*)d_in[2];
    const float* qkv_w  = (const float*)d_in[3];
    const float* qkv_b  = (const float*)d_in[4];
    const float* proj_w = (const float*)d_in[5];
    const float* proj_b = (const float*)d_in[6];
    const float* rel_b  = (const float*)d_in[7];
    const float* se_w1  = (const float*)d_in[8];
    const float* se_b1  = (const float*)d_in[9];
    const float* se_w2  = (const float*)d_in[10];
    const float* se_b2  = (const float*)d_in[11];
    const float* n3_g   = (const float*)d_in[12];
    const float* n3_b   = (const float*)d_in[13];
    const float* mlp_w1 = (const float*)d_in[14];
    const float* mlp_b1 = (const float*)d_in[15];
    const float* mlp_w2 = (const float*)d_in[16];
    const float* mlp_b2 = (const float*)d_in[17];
    float* out = (float*)d_out;

    float *wins, *hbuf, *big, *part, *gate, *wb;
    cudaGetSymbolAddress((void**)&wins, g_wins);
    cudaGetSymbolAddress((void**)&hbuf, g_h);
    cudaGetSymbolAddress((void**)&big,  g_big);
    cudaGetSymbolAddress((void**)&part, g_part);
    cudaGetSymbolAddress((void**)&gate, g_gate);
    cudaGetSymbolAddress((void**)&wb,   g_wb);

    __nv_bfloat16* wbf   = (__nv_bfloat16*)wb;
    __nv_bfloat16* qkvW  = wbf;            // [768,256]
    __nv_bfloat16* projW = wbf + 196608;   // [256,256]
    __nv_bfloat16* w1W   = wbf + 262144;   // [1024,256]
    __nv_bfloat16* w2W   = wbf + 524288;   // [256,1024]
    __nv_bfloat16* bigb  = (__nv_bfloat16*)big;
    __nv_bfloat16* hb    = (__nv_bfloat16*)hbuf;

    cudaFuncSetAttribute(k_gemm_smA, cudaFuncAttributeMaxDynamicSharedMemorySize, SMA_SMEM);
    cudaFuncSetAttribute(k_gemm_sA,  cudaFuncAttributeMaxDynamicSharedMemorySize, SA_SMEM);

    dim3 b328(32, 8);
    dim3 gtr(WW_/32, HH, BATCH*8);

    // exactly 5 launches before the QKV GEMM so ncu -s 5 -c 1 profiles it
    k_winpart<<<gtr, b328>>>(x, wins, part);                      // 1 (also zeroes part)
    k_wprep<<<dim3(24, 8),  b328>>>(qkv_w,  qkvW,  256, 768);     // 2
    k_wprep<<<dim3(8,  8),  b328>>>(proj_w, projW, 256, 256);     // 3
    k_wprep<<<dim3(32, 8),  b328>>>(mlp_w1, w1W,   256, 1024);    // 4
    k_wprep<<<dim3(8,  32), b328>>>(mlp_w2, w2W,   1024, 256);    // 5
    k_gemm_smA<<<NTOK/128, 256, SMA_SMEM>>>(wins, 0, n1_g, n1_b, nullptr,   // 6 <- profiled
                                            qkvW, qkv_b, nullptr,
                                            bigb, 1, 0, 768, nullptr);
    k_attn_tc<<<dim3(NWIN, 2), 128>>>(bigb, rel_b, hb);
    k_gemm_smA<<<NTOK/128, 256, SMA_SMEM>>>(hb, 1, nullptr, nullptr, nullptr,
                                            projW, proj_b, wins,
                                            wins, 0, 0, 256, part);
    k_pool_gate<<<BATCH, 256>>>(part, se_w1, se_b1, se_w2, se_b2, gate);
    k_gemm_smA<<<NTOK/128, 256, SMA_SMEM>>>(wins, 0, n3_g, n3_b, gate,
                                            w1W, mlp_b1, nullptr,
                                            bigb, 1, 1, 1024, nullptr);
    k_gemm_sA<<<NTOK/128, 256, SA_SMEM>>>(bigb, w2W, mlp_b2, wins, gate, hbuf);
    k_winrev<<<gtr, b328>>>(hbuf, out);
}

// round 11
// speedup vs baseline: 1.0091x; 1.0091x over previous
#include <cuda_runtime.h>
#include <cuda_bf16.h>
#include <cstdint>
#include <math.h>

// ---------------------------------------------------------------------------
// HATBlock — Round 11: 64x64 warp tile (CTA 256x128, 1 CTA/SM) for GEMM1;
// wprep merge so ncu's 5th-launch capture = QKV GEMM.
// B=4, C=256, H=W=192, WS=8, NH=8, HD=32
// ---------------------------------------------------------------------------

#define BATCH 4
#define DIM   256
#define HH    192
#define WW_   192
#define NWH   24
#define NWIN  (BATCH*NWH*NWH)   // 2304
#define NTOK  (NWIN*64)         // 147456
#define NH    8
#define TOK_PER_B (HH*WW_)      // 36864

typedef unsigned long long u64;
typedef unsigned int u32;

// -------------------- scratch (device globals; no runtime alloc) -----------
__device__ float g_wins[(size_t)NTOK*256];     // wins / y (fp32)
__device__ float g_h   [(size_t)NTOK*256];     // attn-out bf16 alias / final fp32
__device__ float g_big [(size_t)NTOK*512];     // qkv(768) / hidden(1024) as bf16
__device__ float g_part[1024];                 // pooled sums [B,256]
__device__ float g_gate[BATCH*256];
__device__ float g_wb  [786432/2];             // bf16 weights, transposed [N,K]

__device__ __forceinline__ float gelu_exact(float x) {
    return 0.5f * x * (1.0f + erff(x * 0.70710678118654752f));
}

__device__ __forceinline__ void cp_async16(void* smem, const void* gmem) {
    unsigned s = (unsigned)__cvta_generic_to_shared(smem);
    asm volatile("cp.async.ca.shared.global [%0], [%1], 16;" :: "r"(s), "l"(gmem));
}
__device__ __forceinline__ void cp_commit() { asm volatile("cp.async.commit_group;"); }
__device__ __forceinline__ void cp_wait2()  { asm volatile("cp.async.wait_group 2;" ::: "memory"); }

__device__ __forceinline__ void mma_bf16(float* c, const u32* a, const u32* b) {
    asm volatile(
        "mma.sync.aligned.m16n8k16.row.col.f32.bf16.bf16.f32 "
        "{%0,%1,%2,%3},{%4,%5,%6,%7},{%8,%9},{%0,%1,%2,%3};"
        : "+f"(c[0]), "+f"(c[1]), "+f"(c[2]), "+f"(c[3])
        : "r"(a[0]), "r"(a[1]), "r"(a[2]), "r"(a[3]), "r"(b[0]), "r"(b[1]));
}

__device__ __forceinline__ void ldsm4(u32& r0, u32& r1, u32& r2, u32& r3, u32 addr) {
    asm volatile("ldmatrix.sync.aligned.m8n8.x4.shared.b16 {%0,%1,%2,%3}, [%4];"
                 : "=r"(r0), "=r"(r1), "=r"(r2), "=r"(r3) : "r"(addr));
}

__device__ __forceinline__ u32 packbf(float a, float b) {
    __nv_bfloat162 t = __float22bfloat162_rn(make_float2(a, b));
    return *(u32*)&t;
}

// -------------------- weight prep: fp32 [K,N] -> bf16 [N,K] ----------------
__device__ __forceinline__ void wprep_body(const float* in, __nv_bfloat16* out,
                                           int K, int N, int n0, int k0) {
    __shared__ float tile[32][33];
    for (int r = threadIdx.y; r < 32; r += 8)
        tile[r][threadIdx.x] = in[(size_t)(k0 + r) * N + n0 + threadIdx.x];
    __syncthreads();
    for (int r = threadIdx.y; r < 32; r += 8)
        out[(size_t)(n0 + r) * K + k0 + threadIdx.x] = __float2bfloat16_rn(tile[threadIdx.x][r]);
}

__global__ void k_wprep(const float* __restrict__ in, __nv_bfloat16* __restrict__ out,
                        int K, int N) {
    wprep_body(in, out, K, N, blockIdx.x * 32, blockIdx.y * 32);
}

// two weights in one launch (flattened 1D grid)
__global__ void k_wprep2(const float* __restrict__ inA, __nv_bfloat16* __restrict__ outA,
                         int KA, int NA, int nblkA,
                         const float* __restrict__ inB, __nv_bfloat16* __restrict__ outB,
                         int KB, int NB) {
    int blk = blockIdx.x;
    if (blk < nblkA) {
        int w = NA / 32;
        wprep_body(inA, outA, KA, NA, (blk % w) * 32, (blk / w) * 32);
    } else {
        blk -= nblkA;
        int w = NB / 32;
        wprep_body(inB, outB, KB, NB, (blk % w) * 32, (blk / w) * 32);
    }
}

// -------------------- window partition (+ zero pooled sums) ----------------
__global__ void k_winpart(const float* __restrict__ x, float* __restrict__ wins,
                          float* __restrict__ part) {
    int w0 = blockIdx.x * 32, hh = blockIdx.y;
    int b = blockIdx.z >> 3, c0 = (blockIdx.z & 7) * 32;
    if (blockIdx.x == 0 && blockIdx.y == 0 && blockIdx.z == 0) {
        int t = threadIdx.y * 32 + threadIdx.x;
#pragma unroll
        for (int i = 0; i < 4; i++) part[t + 256*i] = 0.f;
    }
    __shared__ float tile[32][33];
    for (int cc = threadIdx.y; cc < 32; cc += 8)
        tile[cc][threadIdx.x] =
            x[(((size_t)b*256 + c0 + cc)*HH + hh)*WW_ + w0 + threadIdx.x];
    __syncthreads();
    int hw = hh >> 3, i = hh & 7;
    for (int wi = threadIdx.y; wi < 32; wi += 8) {
        int w = w0 + wi, ww = w >> 3, j = w & 7;
        size_t t = (((size_t)b*NWH + hw)*NWH + ww)*64 + i*8 + j;
        wins[t*256 + c0 + threadIdx.x] = tile[threadIdx.x][wi];
    }
}

// -------------------- window reverse: z[t,c] -> out[B,C,H,W] ---------------
__global__ void k_winrev(const float* __restrict__ z, float* __restrict__ out) {
    int w0 = blockIdx.x * 32, hh = blockIdx.y;
    int b = blockIdx.z >> 3, c0 = (blockIdx.z & 7) * 32;
    __shared__ float tile[32][33];
    int hw = hh >> 3, i = hh & 7;
    for (int wi = threadIdx.y; wi < 32; wi += 8) {
        int w = w0 + wi, ww = w >> 3, j = w & 7;
        size_t t = (((size_t)b*NWH + hw)*NWH + ww)*64 + i*8 + j;
        tile[wi][threadIdx.x] = z[t*256 + c0 + threadIdx.x];
    }
    __syncthreads();
    for (int cc = threadIdx.y; cc < 32; cc += 8)
        out[(((size_t)b*256 + c0 + cc)*HH + hh)*WW_ + w0 + threadIdx.x] =
            tile[threadIdx.x][cc];
}

// ============================================================================
// GEMM 1: CTA tile 256x128, 8 warps (4 m x 2 n), warp tile 64x64, K chunk 32.
// A cached in smem bf16 (optionally fused gate+LN from fp32 gmem), 4-stage B.
// smem: Ab bf16[256][264] @0 (135,168B); B ring 4x10,240 @135,168;
//       scol[128] fp32 @176,128.  Total 176,640 -> 1 CTA/SM.
// ============================================================================
#define AB_STR 264
#define B_STR  40
#define SMA_BR   135168
#define SMA_SCOL 176128
#define SMA_SMEM 176640

__global__ void __launch_bounds__(256, 1)
k_gemm_smA(const void* __restrict__ Ain, int a_bf16,
           const float* __restrict__ lng, const float* __restrict__ lnb,
           const float* __restrict__ gate,
           const __nv_bfloat16* __restrict__ Wt,
           const float* __restrict__ bias,
           const float* __restrict__ R,
           void* __restrict__ Cout, int c_bf16, int act,
           int Nfull, float* __restrict__ pool)
{
    extern __shared__ char smem[];
    __nv_bfloat16* Ab = (__nv_bfloat16*)smem;
    char*  Bring = smem + SMA_BR;
    float* scol = (float*)(smem + SMA_SCOL);
    const u32 sbase = (u32)__cvta_generic_to_shared(smem);

    const int tid = threadIdx.x, lane = tid & 31, wid = tid >> 5;
    const int g = lane >> 2, tig = lane & 3;
    const int arow = (wid & 3) * 64;     // 4 m-warps cover 256 rows
    const int bcol = (wid >> 2) * 64;    // 2 n-warps cover 128 cols
    const int m0 = blockIdx.x * 256;
    const int b  = m0 / TOK_PER_B;

    const int a_dr = (lane & 7) | (((lane >> 3) & 1) << 3);
    const int a_dk = (lane >> 4) << 3;
    const int quad = lane >> 3;
    const int b_dc = (lane & 7) + ((quad & 2) ? 8 : 0);
    const int b_dk = (quad & 1) << 3;

    // ---- load A (256 rows x 256 cols) ----
    if (a_bf16) {
        const __nv_bfloat16* Ag = (const __nv_bfloat16*)Ain + (size_t)m0 * 256;
#pragma unroll
        for (int i = 0; i < 32; i++) {
            int idx = tid + 256*i;
            int r = idx >> 5, c8 = idx & 31;
            cp_async16(Ab + r*AB_STR + c8*8, Ag + (size_t)r*256 + c8*8);
        }
        cp_commit();
    } else {
        const float* Ag = (const float*)Ain + (size_t)m0 * 256;
        const float* gp = gate ? (gate + b*256) : nullptr;
        float gv[8], lg[8], lb[8];
#pragma unroll
        for (int j = 0; j < 8; j++) {
            int c = lane*8 + j;
            gv[j] = gp ? gp[c] : 1.f;
            lg[j] = lng[c]; lb[j] = lnb[c];
        }
#pragma unroll 1
        for (int i = 0; i < 32; i++) {
            int r = wid*32 + i;
            const float4* rp = (const float4*)(Ag + (size_t)r * 256 + lane*8);
            float4 va = rp[0], vb = rp[1];
            float v[8] = {va.x, va.y, va.z, va.w, vb.x, vb.y, vb.z, vb.w};
            float s = 0.f, s2 = 0.f;
#pragma unroll
            for (int j = 0; j < 8; j++) {
                v[j] *= gv[j]; s += v[j]; s2 += v[j]*v[j];
            }
#pragma unroll
            for (int o = 16; o; o >>= 1) {
                s  += __shfl_xor_sync(0xffffffffu, s,  o);
                s2 += __shfl_xor_sync(0xffffffffu, s2, o);
            }
            float mean = s * (1.f/256.f);
            float var  = s2 * (1.f/256.f) - mean*mean;
            float inv  = rsqrtf(var + 1e-5f);
#pragma unroll
            for (int k = 0; k < 4; k++) {
                float n0 = (v[2*k  ]-mean)*inv*lg[2*k  ] + lb[2*k  ];
                float n1 = (v[2*k+1]-mean)*inv*lg[2*k+1] + lb[2*k+1];
                *(u32*)&Ab[r*AB_STR + lane*8 + 2*k] = packbf(n0, n1);
            }
        }
        __syncthreads();
    }

    const int NY = Nfull >> 7;
    const int KT = 8;
    const int TOT = NY * KT;

    auto fillB = [&](int c) {
        int ny2 = c >> 3, kt2 = c & 7, st = c & 3;
        __nv_bfloat16* Bs = (__nv_bfloat16*)(Bring + st*10240);
        const __nv_bfloat16* Wg = Wt + (size_t)(ny2*128) * 256 + kt2*32;
#pragma unroll
        for (int i = 0; i < 2; i++) {
            int idx = tid + 256*i;
            int row = idx >> 2, seg = idx & 3;
            cp_async16(Bs + row*B_STR + seg*8, Wg + (size_t)row*256 + seg*8);
        }
        cp_commit();
    };
    fillB(0); fillB(1); fillB(2);

    int ci = 0;
    for (int ny = 0; ny < NY; ny++) {
        float acc[4][8][4];
#pragma unroll
        for (int i = 0; i < 4; i++)
#pragma unroll
            for (int j = 0; j < 8; j++)
#pragma unroll
                for (int q = 0; q < 4; q++) acc[i][j][q] = 0.f;

        for (int kt = 0; kt < KT; kt++, ci++) {
            cp_wait2();
            __syncthreads();
            const u32 bsb = sbase + SMA_BR + (u32)(ci & 3)*10240;
#pragma unroll
            for (int ks = 0; ks < 2; ks++) {
                const int kb = kt*32 + ks*16;
                u32 af[4][4], bf[8][2];
#pragma unroll
                for (int mt = 0; mt < 4; mt++) {
                    u32 aaddr = sbase + (u32)(((arow + mt*16 + a_dr)*AB_STR + kb + a_dk) * 2);
                    ldsm4(af[mt][0], af[mt][1], af[mt][2], af[mt][3], aaddr);
                }
#pragma unroll
                for (int p = 0; p < 4; p++) {
                    u32 baddr = bsb + (u32)(((bcol + p*16 + b_dc)*B_STR + ks*16 + b_dk) * 2);
                    ldsm4(bf[2*p][0], bf[2*p][1], bf[2*p+1][0], bf[2*p+1][1], baddr);
                }
#pragma unroll
                for (int mt = 0; mt < 4; mt++)
#pragma unroll
                    for (int nt = 0; nt < 8; nt++)
                        mma_bf16(acc[mt][nt], af[mt], bf[nt]);
            }
            if (ci + 3 < TOT) fillB(ci + 3);
            else cp_commit();
        }

        const int ncol0 = ny * 128;
        if (c_bf16) {
            __nv_bfloat16* Cb = (__nv_bfloat16*)Cout;
#pragma unroll
            for (int nt = 0; nt < 8; nt++) {
                int colG = ncol0 + bcol + nt*8 + 2*tig;
                float b0 = bias[colG], b1 = bias[colG + 1];
#pragma unroll
                for (int mt = 0; mt < 4; mt++) {
                    size_t r0 = (size_t)m0 + arow + mt*16 + g;
                    size_t r1 = r0 + 8;
                    float v00 = acc[mt][nt][0] + b0, v01 = acc[mt][nt][1] + b1;
                    float v10 = acc[mt][nt][2] + b0, v11 = acc[mt][nt][3] + b1;
                    if (act) {
                        v00 = gelu_exact(v00); v01 = gelu_exact(v01);
                        v10 = gelu_exact(v10); v11 = gelu_exact(v11);
                    }
                    *(u32*)((__nv_bfloat16*)Cb + r0*Nfull + colG) = packbf(v00, v01);
                    *(u32*)((__nv_bfloat16*)Cb + r1*Nfull + colG) = packbf(v10, v11);
                }
            }
        } else {
            float* Cf = (float*)Cout;
            float psum[8][2];
#pragma unroll
            for (int nt = 0; nt < 8; nt++) { psum[nt][0] = 0.f; psum[nt][1] = 0.f; }
#pragma unroll
            for (int nt = 0; nt < 8; nt++) {
                int colG = ncol0 + bcol + nt*8 + 2*tig;
                float b0 = bias[colG], b1 = bias[colG + 1];
#pragma unroll
                for (int mt = 0; mt < 4; mt++) {
                    size_t r0 = (size_t)m0 + arow + mt*16 + g;
                    size_t r1 = r0 + 8;
                    float2 q0 = *(const float2*)(R + r0*Nfull + colG);
                    float2 q1 = *(const float2*)(R + r1*Nfull + colG);
                    float v00 = acc[mt][nt][0] + b0 + q0.x, v01 = acc[mt][nt][1] + b1 + q0.y;
                    float v10 = acc[mt][nt][2] + b0 + q1.x, v11 = acc[mt][nt][3] + b1 + q1.y;
                    *(float2*)(Cf + r0*Nfull + colG) = make_float2(v00, v01);
                    *(float2*)(Cf + r1*Nfull + colG) = make_float2(v10, v11);
                    psum[nt][0] += v00 + v10; psum[nt][1] += v01 + v11;
                }
            }
            if (pool) {
                __syncthreads();
                if (tid < 128) scol[tid] = 0.f;
                __syncthreads();
#pragma unroll
                for (int nt = 0; nt < 8; nt++) {
                    int colL = bcol + nt*8 + 2*tig;
                    atomicAdd(&scol[colL],     psum[nt][0]);
                    atomicAdd(&scol[colL + 1], psum[nt][1]);
                }
                __syncthreads();
                if (tid < 128) atomicAdd(pool + b*256 + ncol0 + tid, scol[tid]);
                __syncthreads();
            }
        }
    }
}

// ============================================================================
// GEMM 2 (MLP2): A bf16 streamed [M,1024], Wt bf16 [256,1024], N-loop (2).
// ============================================================================
#define SA_SMEM 81920
__global__ void __launch_bounds__(256, 2)
k_gemm_sA(const __nv_bfloat16* __restrict__ Ain,
          const __nv_bfloat16* __restrict__ Wt,
          const float* __restrict__ bias,
          const float* __restrict__ R,
          const float* __restrict__ gate,
          float* __restrict__ Cout)
{
    extern __shared__ char smem[];
    const u32 sbase = (u32)__cvta_generic_to_shared(smem);
    const int tid = threadIdx.x, lane = tid & 31, wid = tid >> 5;
    const int g = lane >> 2, tig = lane & 3;
    const int arow = (wid & 3) * 32;
    const int bcol = (wid >> 2) * 64;
    const int m0 = blockIdx.x * 128;
    const int b  = m0 / TOK_PER_B;
    const int KT = 32, NY = 2, TOT = 64;

    const int a_dr = (lane & 7) | (((lane >> 3) & 1) << 3);
    const int a_dk = (lane >> 4) << 3;
    const int quad = lane >> 3;
    const int b_dc = (lane & 7) + ((quad & 2) ? 8 : 0);
    const int b_dk = (quad & 1) << 3;

    const __nv_bfloat16* Ag = Ain + (size_t)m0 * 1024;

    auto fillC = [&](int c) {
        int ny2 = c >> 5, kt2 = c & 31, st = c & 3;
        __nv_bfloat16* As = (__nv_bfloat16*)(smem + st*10240);
        __nv_bfloat16* Bs = (__nv_bfloat16*)(smem + 40960 + st*10240);
        const __nv_bfloat16* Wg = Wt + (size_t)(ny2*128) * 1024 + kt2*32;
        const __nv_bfloat16* Ac = Ag + kt2*32;
#pragma unroll
        for (int i = 0; i < 2; i++) {
            int idx = tid + 256*i;
            int row = idx >> 2, seg = idx & 3;
            cp_async16(As + row*B_STR + seg*8, Ac + (size_t)row*1024 + seg*8);
            cp_async16(Bs + row*B_STR + seg*8, Wg + (size_t)row*1024 + seg*8);
        }
        cp_commit();
    };
    fillC(0); fillC(1); fillC(2);

    int ci = 0;
    for (int ny = 0; ny < NY; ny++) {
        float acc[2][8][4];
#pragma unroll
        for (int i = 0; i < 2; i++)
#pragma unroll
            for (int j = 0; j < 8; j++)
#pragma unroll
                for (int q = 0; q < 4; q++) acc[i][j][q] = 0.f;

        for (int kt = 0; kt < KT; kt++, ci++) {
            cp_wait2();
            __syncthreads();
            int st = ci & 3;
            const u32 asb = sbase + (u32)st*10240;
            const u32 bsb = sbase + 40960u + (u32)st*10240;
#pragma unroll
            for (int ks = 0; ks < 2; ks++) {
                u32 af[2][4], bf[8][2];
#pragma unroll
                for (int mt = 0; mt < 2; mt++) {
                    u32 aaddr = asb + (u32)(((arow + mt*16 + a_dr)*B_STR + ks*16 + a_dk) * 2);
                    ldsm4(af[mt][0], af[mt][1], af[mt][2], af[mt][3], aaddr);
                }
#pragma unroll
                for (int p = 0; p < 4; p++) {
                    u32 baddr = bsb + (u32)(((bcol + p*16 + b_dc)*B_STR + ks*16 + b_dk) * 2);
                    ldsm4(bf[2*p][0], bf[2*p][1], bf[2*p+1][0], bf[2*p+1][1], baddr);
                }
#pragma unroll
                for (int mt = 0; mt < 2; mt++)
#pragma unroll
                    for (int nt = 0; nt < 8; nt++)
                        mma_bf16(acc[mt][nt], af[mt], bf[nt]);
            }
            if (ci + 3 < TOT) fillC(ci + 3);
            else cp_commit();
        }

        const int ncol0 = ny * 128;
#pragma unroll
        for (int nt = 0; nt < 8; nt++) {
            int colG = ncol0 + bcol + nt*8 + 2*tig;
            float b0 = bias[colG], b1 = bias[colG + 1];
            float g0 = gate[b*256 + colG], g1 = gate[b*256 + colG + 1];
#pragma unroll
            for (int mt = 0; mt < 2; mt++) {
                size_t r0 = (size_t)m0 + arow + mt*16 + g;
                size_t r1 = r0 + 8;
                float2 q0 = *(const float2*)(R + r0*256 + colG);
                float2 q1 = *(const float2*)(R + r1*256 + colG);
                float v00 = acc[mt][nt][0] + b0 + q0.x*g0, v01 = acc[mt][nt][1] + b1 + q0.y*g1;
                float v10 = acc[mt][nt][2] + b0 + q1.x*g0, v11 = acc[mt][nt][3] + b1 + q1.y*g1;
                *(float2*)(Cout + r0*256 + colG) = make_float2(v00, v01);
                *(float2*)(Cout + r1*256 + colG) = make_float2(v10, v11);
            }
        }
    }
}

// ============================================================================
// Tensor-core window attention: one warp per (window, head).
// ============================================================================
__global__ void __launch_bounds__(128) k_attn_tc(const __nv_bfloat16* __restrict__ qkv,
                                                 const float* __restrict__ rel_bias,
                                                 __nv_bfloat16* __restrict__ o) {
    __shared__ __align__(16) __nv_bfloat16 VtAll[4][32][72];
    __shared__ float sbAll[4][226];

    const int lane = threadIdx.x & 31;
    const int wid  = threadIdx.x >> 5;
    const int g = lane >> 2, tig = lane & 3;
    const int win = blockIdx.x;
    const int h = blockIdx.y * 4 + wid;

    __nv_bfloat16 (*Vt)[72] = VtAll[wid];
    float* sb = sbAll[wid];
    const u32 vtb = (u32)__cvta_generic_to_shared(&VtAll[wid][0][0]);

    const int quad = lane >> 3;
    const int v_dc = (lane & 7) + ((quad & 2) ? 8 : 0);
    const int v_dk = (quad & 1) << 3;

    const __nv_bfloat16* qw = qkv + (size_t)win * 64 * 768 + h * 32;
    const __nv_bfloat16* kw = qw + 256;
    const __nv_bfloat16* vw = qw + 512;

    for (int r = lane; r < 225; r += 32) sb[r] = rel_bias[r*NH + h];

#pragma unroll
    for (int i = 0; i < 32; i++) {
        int idx = lane + 32*i;
        int n = idx >> 4, dp = idx & 15;
        u32 u = *(const u32*)(vw + (size_t)n*768 + 2*dp);
        __nv_bfloat162 v2 = *(__nv_bfloat162*)&u;
        Vt[2*dp  ][n] = v2.x;
        Vt[2*dp+1][n] = v2.y;
    }
    __syncwarp();

    u32 aQ[2][4][4];
#pragma unroll
    for (int ks = 0; ks < 2; ks++) {
        const int kc = 16*ks + 2*tig;
#pragma unroll
        for (int mt = 0; mt < 4; mt++) {
            const __nv_bfloat16* q0 = qw + (size_t)(mt*16 + g)*768 + kc;
            aQ[ks][mt][0] = *(const u32*)(q0);
            aQ[ks][mt][1] = *(const u32*)(q0 + 8*768);
            aQ[ks][mt][2] = *(const u32*)(q0 + 8);
            aQ[ks][mt][3] = *(const u32*)(q0 + 8*768 + 8);
        }
    }

    float O[4][4][4];
#pragma unroll
    for (int a = 0; a < 4; a++)
#pragma unroll
        for (int bq = 0; bq < 4; bq++)
#pragma unroll
            for (int c = 0; c < 4; c++) O[a][bq][c] = 0.f;
    float mrow[8], lrow[8];
#pragma unroll
    for (int r = 0; r < 8; r++) { mrow[r] = -1e30f; lrow[r] = 0.f; }

#pragma unroll 1
    for (int ck = 0; ck < 2; ck++) {
        float S[4][4][4];
#pragma unroll
        for (int a = 0; a < 4; a++)
#pragma unroll
            for (int bq = 0; bq < 4; bq++)
#pragma unroll
                for (int c = 0; c < 4; c++) S[a][bq][c] = 0.f;

#pragma unroll
        for (int ks = 0; ks < 2; ks++) {
            const int kc = 16*ks + 2*tig;
            u32 bK[4][2];
#pragma unroll
            for (int nt = 0; nt < 4; nt++) {
                const __nv_bfloat16* k0 = kw + (size_t)(ck*32 + nt*8 + g)*768 + kc;
                bK[nt][0] = *(const u32*)(k0);
                bK[nt][1] = *(const u32*)(k0 + 8);
            }
#pragma unroll
            for (int mt = 0; mt < 4; mt++)
#pragma unroll
                for (int nt = 0; nt < 4; nt++)
                    mma_bf16(S[mt][nt], aQ[ks][mt], bK[nt]);
        }

#pragma unroll
        for (int mt = 0; mt < 4; mt++)
#pragma unroll
            for (int nt = 0; nt < 4; nt++)
#pragma unroll
                for (int rr = 0; rr < 2; rr++)
#pragma unroll
                    for (int e = 0; e < 2; e++) {
                        int di = 2*mt + rr - (4*ck + nt) + 7;
                        int dj = g - (2*tig + e) + 7;
                        S[mt][nt][rr*2+e] = S[mt][nt][rr*2+e] * 0.17677669529663687f
                                          + sb[di*15 + dj];
                    }

#pragma unroll
        for (int mt = 0; mt < 4; mt++)
#pragma unroll
            for (int rr = 0; rr < 2; rr++) {
                const int r8 = mt*2 + rr;
                float mloc = -1e30f;
#pragma unroll
                for (int nt = 0; nt < 4; nt++) {
                    mloc = fmaxf(mloc, S[mt][nt][rr*2]);
                    mloc = fmaxf(mloc, S[mt][nt][rr*2+1]);
                }
                mloc = fmaxf(mloc, __shfl_xor_sync(0xffffffffu, mloc, 1));
                mloc = fmaxf(mloc, __shfl_xor_sync(0xffffffffu, mloc, 2));
                float newm = fmaxf(mrow[r8], mloc);
                float fsc = __expf(mrow[r8] - newm);
                mrow[r8] = newm;
                float rsum = 0.f;
#pragma unroll
                for (int nt = 0; nt < 4; nt++) {
                    float p0 = __expf(S[mt][nt][rr*2]   - newm);
                    float p1 = __expf(S[mt][nt][rr*2+1] - newm);
                    S[mt][nt][rr*2] = p0; S[mt][nt][rr*2+1] = p1;
                    rsum += p0 + p1;
                }
                rsum += __shfl_xor_sync(0xffffffffu, rsum, 1);
                rsum += __shfl_xor_sync(0xffffffffu, rsum, 2);
                lrow[r8] = lrow[r8]*fsc + rsum;
#pragma unroll
                for (int nt2 = 0; nt2 < 4; nt2++) {
                    O[mt][nt2][rr*2]   *= fsc;
                    O[mt][nt2][rr*2+1] *= fsc;
                }
            }

#pragma unroll
        for (int ks2 = 0; ks2 < 2; ks2++) {
            u32 bV[4][2];
#pragma unroll
            for (int p = 0; p < 2; p++) {
                u32 vaddr = vtb + (u32)(((p*16 + v_dc)*72 + ck*32 + ks2*16 + v_dk) * 2);
                ldsm4(bV[2*p][0], bV[2*p][1], bV[2*p+1][0], bV[2*p+1][1], vaddr);
            }
#pragma unroll
            for (int mt = 0; mt < 4; mt++) {
                u32 pa[4];
                pa[0] = packbf(S[mt][2*ks2  ][0], S[mt][2*ks2  ][1]);
                pa[1] = packbf(S[mt][2*ks2  ][2], S[mt][2*ks2  ][3]);
                pa[2] = packbf(S[mt][2*ks2+1][0], S[mt][2*ks2+1][1]);
                pa[3] = packbf(S[mt][2*ks2+1][2], S[mt][2*ks2+1][3]);
#pragma unroll
                for (int nt2 = 0; nt2 < 4; nt2++)
                    mma_bf16(O[mt][nt2], pa, bV[nt2]);
            }
        }
    }

    float invl[8];
#pragma unroll
    for (int r = 0; r < 8; r++) invl[r] = 1.f / lrow[r];
    __nv_bfloat16* ob = o + (size_t)win * 64 * 256 + h * 32;
#pragma unroll
    for (int mt = 0; mt < 4; mt++)
#pragma unroll
        for (int nt2 = 0; nt2 < 4; nt2++) {
            __nv_bfloat16* p0 = ob + (size_t)(mt*16 + g)*256 + nt2*8 + 2*tig;
            *(u32*)(p0)         = packbf(O[mt][nt2][0]*invl[2*mt],   O[mt][nt2][1]*invl[2*mt]);
            *(u32*)(p0 + 8*256) = packbf(O[mt][nt2][2]*invl[2*mt+1], O[mt][nt2][3]*invl[2*mt+1]);
        }
}

// -------------------- SE gate from completed pooled sums --------------------
__global__ void __launch_bounds__(256) k_pool_gate(const float* __restrict__ part,
                                                   const float* __restrict__ w1,
                                                   const float* __restrict__ b1,
                                                   const float* __restrict__ w2,
                                                   const float* __restrict__ b2,
                                                   float* __restrict__ gate) {
    int b = blockIdx.x;
    float pooled = part[b*256 + threadIdx.x] * (1.f / (float)TOK_PER_B);
    __shared__ float sp[256];
    __shared__ float hid[16];
    sp[threadIdx.x] = pooled;
    __syncthreads();
    if (threadIdx.x < 16) {
        float a = b1[threadIdx.x];
        for (int c = 0; c < 256; c++) a = fmaf(sp[c], w1[c*16 + threadIdx.x], a);
        hid[threadIdx.x] = fmaxf(a, 0.f);
    }
    __syncthreads();
    float g = b2[threadIdx.x];
#pragma unroll
    for (int j = 0; j < 16; j++) g = fmaf(hid[j], w2[j*256 + threadIdx.x], g);
    gate[b*256 + threadIdx.x] = 1.f / (1.f + __expf(-g));
}

// ---------------------------------------------------------------------------
extern "C" void kernel_launch(void* const* d_in, const int* in_sizes, int n_in,
                              void* d_out, int out_size) {
    const float* x      = (const float*)d_in[0];
    const float* n1_g   = (const float*)d_in[1];
    const float* n1_b   = (const float*)d_in[2];
    const float* qkv_w  = (const float*)d_in[3];
    const float* qkv_b  = (const float*)d_in[4];
    const float* proj_w = (const float*)d_in[5];
    const float* proj_b = (const float*)d_in[6];
    const float* rel_b  = (const float*)d_in[7];
    const float* se_w1  = (const float*)d_in[8];
    const float* se_b1  = (const float*)d_in[9];
    const float* se_w2  = (const float*)d_in[10];
    const float* se_b2  = (const float*)d_in[11];
    const float* n3_g   = (const float*)d_in[12];
    const float* n3_b   = (const float*)d_in[13];
    const float* mlp_w1 = (const float*)d_in[14];
    const float* mlp_b1 = (const float*)d_in[15];
    const float* mlp_w2 = (const float*)d_in[16];
    const float* mlp_b2 = (const float*)d_in[17];
    float* out = (float*)d_out;

    float *wins, *hbuf, *big, *part, *gate, *wb;
    cudaGetSymbolAddress((void**)&wins, g_wins);
    cudaGetSymbolAddress((void**)&hbuf, g_h);
    cudaGetSymbolAddress((void**)&big,  g_big);
    cudaGetSymbolAddress((void**)&part, g_part);
    cudaGetSymbolAddress((void**)&gate, g_gate);
    cudaGetSymbolAddress((void**)&wb,   g_wb);

    __nv_bfloat16* wbf   = (__nv_bfloat16*)wb;
    __nv_bfloat16* qkvW  = wbf;            // [768,256]
    __nv_bfloat16* projW = wbf + 196608;   // [256,256]
    __nv_bfloat16* w1W   = wbf + 262144;   // [1024,256]
    __nv_bfloat16* w2W   = wbf + 524288;   // [256,1024]
    __nv_bfloat16* bigb  = (__nv_bfloat16*)big;
    __nv_bfloat16* hb    = (__nv_bfloat16*)hbuf;

    cudaFuncSetAttribute(k_gemm_smA, cudaFuncAttributeMaxDynamicSharedMemorySize, SMA_SMEM);
    cudaFuncSetAttribute(k_gemm_sA,  cudaFuncAttributeMaxDynamicSharedMemorySize, SA_SMEM);

    dim3 b328(32, 8);
    dim3 gtr(WW_/32, HH, BATCH*8);

    // ncu profiles the 5th launch -> make it the QKV GEMM.
    k_winpart<<<gtr, b328>>>(x, wins, part);                          // 1
    k_wprep<<<dim3(24, 8),  b328>>>(qkv_w,  qkvW,  256, 768);         // 2
    k_wprep<<<dim3(32, 8),  b328>>>(mlp_w1, w1W,   256, 1024);        // 3
    k_wprep2<<<320, b328>>>(proj_w, projW, 256, 256, 64,              // 4 (proj + w2)
                            mlp_w2, w2W, 1024, 256);
    k_gemm_smA<<<NTOK/256, 256, SMA_SMEM>>>(wins, 0, n1_g, n1_b, nullptr,  // 5 <- profiled
                                            qkvW, qkv_b, nullptr,
                                            bigb, 1, 0, 768, nullptr);
    k_attn_tc<<<dim3(NWIN, 2), 128>>>(bigb, rel_b, hb);
    k_gemm_smA<<<NTOK/256, 256, SMA_SMEM>>>(hb, 1, nullptr, nullptr, nullptr,
                                            projW, proj_b, wins,
                                            wins, 0, 0, 256, part);
    k_pool_gate<<<BATCH, 256>>>(part, se_w1, se_b1, se_w2, se_b2, gate);
    k_gemm_smA<<<NTOK/256, 256, SMA_SMEM>>>(wins, 0, n3_g, n3_b, gate,
                                            w1W, mlp_b1, nullptr,
                                            bigb, 1, 1, 1024, nullptr);
    k_gemm_sA<<<NTOK/128, 256, SA_SMEM>>>(bigb, w2W, mlp_b2, wins, gate, hbuf);
    k_winrev<<<gtr, b328>>>(hbuf, out);
}